// round 13
// baseline (speedup 1.0000x reference)
#include <cuda_runtime.h>
#include <math.h>
#include <stdint.h>

#define NB 16
#define NN 2048
#define NM 64
#define NR 4
#define NH 512
#define NCIN 320
#define NCOUT 535
#define NKEYS 5
#define FEPS 1e-8f
#define NTILE 16          // row tiles per batch in k_link (128 rows each)

// ---- output layout (tuple flattened in reference return order) ----
#define OUT_OUTPUT 0
#define OUT_MEM    ((size_t)(NB*64))
#define OUT_LINK   (OUT_MEM + (size_t)NB*NN*NM)
#define OUT_P      (OUT_LINK + (size_t)NB*NN*NN)
#define OUT_USAGE  (OUT_P + (size_t)NB*NN)
#define OUT_READW  (OUT_USAGE + (size_t)NB*NN)

// ---- scratch (static device globals; no allocation) ----
__device__ float g_gates[NB*4*NH];
__device__ float g_keys[NB*NKEYS*NM];
__device__ float g_betas[NB*NKEYS];
__device__ float g_free[NB*NR];
__device__ float g_erase[NB*NM];
__device__ float g_wvec[NB*NM];
__device__ float g_agate[NB];
__device__ float g_wgate[NB];
__device__ float g_modes[NB*NR*3];      // raw logits
__device__ float g_taskout[NB*64];
__device__ float g_cw[NB*NKEYS*NN];     // raw beta*sim logits (never normalized in place)
__device__ float g_sstat[NB*NKEYS*2];   // per (b,key): max, inv-sum
__device__ float g_ww[NB*NN];
__device__ float g_fwd[NB*NR*NN];
__device__ float g_bwdp[(size_t)NTILE*NB*NR*NN];   // per-tile bwd partial slabs
__device__ float g_reads[NB*NR*NM];

__device__ __forceinline__ float sigm(float x){ return 1.0f/(1.0f+expf(-x)); }
__device__ __forceinline__ float softplusf(float x){ return fmaxf(x,0.0f) + log1pf(expf(-fabsf(x))); }

// 4-value warp multireduce: after this, lanes with (lane&3)==c hold sum_c.
__device__ __forceinline__ float multireduce4(float f0, float f1, float f2, float f3, int lane){
    float a01 = (lane & 1) ? f0 : f1;
    float r01 = __shfl_xor_sync(0xffffffffu, a01, 1);
    float u = (lane & 1) ? (f1 + r01) : (f0 + r01);
    float a23 = (lane & 1) ? f2 : f3;
    float r23 = __shfl_xor_sync(0xffffffffu, a23, 1);
    float w = (lane & 1) ? (f3 + r23) : (f2 + r23);
    float a2 = (lane & 2) ? u : w;
    float r2 = __shfl_xor_sync(0xffffffffu, a2, 2);
    float v = (lane & 2) ? (w + r2) : (u + r2);
    v += __shfl_xor_sync(0xffffffffu, v, 4);
    v += __shfl_xor_sync(0xffffffffu, v, 8);
    v += __shfl_xor_sync(0xffffffffu, v, 16);
    return v;
}

// bitonic in-warp substage for element index i, stage k, distance j (j<=16)
__device__ __forceinline__ unsigned long long bsub(unsigned long long e, int i, int j, int k){
    unsigned long long o = __shfl_xor_sync(0xffffffffu, e, j);
    bool takeMin = (((i & j) == 0) == ((i & k) == 0));
    bool gt = e > o;
    return (takeMin == gt) ? o : e;
}

// ================= K1: LSTM gates — warp computes one g for 4 batches =========
__global__ void k_gates(const float* __restrict__ task, const float* __restrict__ prev_reads,
                        const float* __restrict__ h_prev, const float* __restrict__ W_ih,
                        const float* __restrict__ W_hh, const float* __restrict__ b_lstm){
    int w = (blockIdx.x*blockDim.x + threadIdx.x) >> 5;   // 8192 warps
    int lane = threadIdx.x & 31;
    int bg = w & 3;             // batch group (4 batches each)
    int g = w >> 2;             // 0..2047
    int b0 = bg*4;
    float a0 = 0.f, a1 = 0.f, a2 = 0.f, a3 = 0.f;
    const float2* wi = (const float2*)(W_ih + (size_t)g*NCIN);
    const float2* t2 = (const float2*)task;          // [b][32]
    const float2* r2 = (const float2*)prev_reads;    // [b][128]
    #pragma unroll
    for (int k2 = lane, it = 0; it < 5; k2 += 32, it++){
        float2 wv = wi[k2];
        float2 x0, x1, x2, x3;
        if (k2 < 32){
            x0 = t2[(b0+0)*32 + k2]; x1 = t2[(b0+1)*32 + k2];
            x2 = t2[(b0+2)*32 + k2]; x3 = t2[(b0+3)*32 + k2];
        } else {
            int kk = k2 - 32;
            x0 = r2[(b0+0)*128 + kk]; x1 = r2[(b0+1)*128 + kk];
            x2 = r2[(b0+2)*128 + kk]; x3 = r2[(b0+3)*128 + kk];
        }
        a0 = fmaf(wv.x, x0.x, fmaf(wv.y, x0.y, a0));
        a1 = fmaf(wv.x, x1.x, fmaf(wv.y, x1.y, a1));
        a2 = fmaf(wv.x, x2.x, fmaf(wv.y, x2.y, a2));
        a3 = fmaf(wv.x, x3.x, fmaf(wv.y, x3.y, a3));
    }
    const float2* wh = (const float2*)(W_hh + (size_t)g*NH);
    const float2* h2 = (const float2*)h_prev;        // [b][256]
    #pragma unroll
    for (int k2 = lane, it = 0; it < 8; k2 += 32, it++){
        float2 wv = wh[k2];
        float2 x0 = h2[(b0+0)*256 + k2], x1 = h2[(b0+1)*256 + k2];
        float2 x2 = h2[(b0+2)*256 + k2], x3 = h2[(b0+3)*256 + k2];
        a0 = fmaf(wv.x, x0.x, fmaf(wv.y, x0.y, a0));
        a1 = fmaf(wv.x, x1.x, fmaf(wv.y, x1.y, a1));
        a2 = fmaf(wv.x, x2.x, fmaf(wv.y, x2.y, a2));
        a3 = fmaf(wv.x, x3.x, fmaf(wv.y, x3.y, a3));
    }
    float v = multireduce4(a0, a1, a2, a3, lane);
    if (lane < 4) g_gates[(b0 + lane)*(4*NH) + g] = v + b_lstm[g];
}

// ================= K2: fused LSTM cell + output projection + parse =============
__global__ void k_ctrl(const float* __restrict__ c_prev, const float* __restrict__ W_out,
                       const float* __restrict__ b_out){
    __shared__ float h_sh[NH];
    int b = blockIdx.x >> 2;
    int part = blockIdx.x & 3;
    int tid = threadIdx.x;
    if (part == 0 && tid < NR*NM) g_reads[b*(NR*NM) + tid] = 0.0f;
    {
        const float* gb = g_gates + b*(4*NH);
        float gi = gb[tid], gf = gb[NH+tid], gg = gb[2*NH+tid], go = gb[3*NH+tid];
        float c = sigm(gf)*c_prev[b*NH+tid] + sigm(gi)*tanhf(gg);
        h_sh[tid] = sigm(go)*tanhf(c);
    }
    __syncthreads();
    int warp = tid >> 5, lane = tid & 31;
    int gw = part*16 + warp;      // 0..63
    const float2* h2 = (const float2*)h_sh;
    for (int o = gw; o < NCOUT; o += 64){
        float acc = 0.0f;
        const float2* w2 = (const float2*)(W_out + (size_t)o*NH);
        #pragma unroll
        for (int k2 = lane, it = 0; it < 8; k2 += 32, it++){
            float2 wv = w2[k2], xv = h2[k2];
            acc = fmaf(wv.x, xv.x, fmaf(wv.y, xv.y, acc));
        }
        #pragma unroll
        for (int s = 16; s; s >>= 1) acc += __shfl_xor_sync(0xffffffffu, acc, s);
        if (lane == 0){
            float v = acc + b_out[o];
            int c = o;
            if (c < 64)        g_taskout[b*64 + c] = sigm(v);
            else if (c < 320)  g_keys[b*NKEYS*NM + (c-64)] = sigm(v);
            else if (c < 324)  g_betas[b*NKEYS + (c-320)] = 1.0f + softplusf(v);
            else if (c < 328)  g_free[b*NR + (c-324)] = sigm(v);
            else if (c < 392)  g_keys[b*NKEYS*NM + 4*NM + (c-328)] = sigm(v);
            else if (c == 392) g_betas[b*NKEYS + 4] = 1.0f + softplusf(v);
            else if (c < 457)  g_erase[b*NM + (c-393)] = sigm(v);
            else if (c < 521)  g_wvec[b*NM + (c-457)] = sigm(v);
            else if (c == 521) g_agate[b] = sigm(v);
            else if (c == 522) g_wgate[b] = sigm(v);
            else               g_modes[b*12 + (c-523)] = v;
        }
    }
}

// ================= K3: cosine similarity logits (beta*sim), 512 blocks =========
__global__ void k_sim(const float* __restrict__ memory){
    __shared__ float keys_sh[NKEYS*NM];
    __shared__ float beta_sh[NKEYS], kn_sh[NKEYS];
    int b = blockIdx.x >> 5;
    int tile = blockIdx.x & 31;
    int tid = threadIdx.x;
    for (int i = tid; i < NKEYS*NM; i += blockDim.x) keys_sh[i] = g_keys[b*NKEYS*NM + i];
    if (tid < NKEYS) beta_sh[tid] = g_betas[b*NKEYS+tid];
    __syncthreads();
    if (tid < NKEYS){
        float s = 0.0f;
        #pragma unroll 8
        for (int i = 0; i < NM; i++){ float x = keys_sh[tid*NM+i]; s += x*x; }
        kn_sh[tid] = sqrtf(s);
    }
    __syncthreads();
    int warp = tid >> 5, lane = tid & 31;
    #pragma unroll
    for (int rr = 0; rr < 8; rr++){
        int n = tile*64 + warp*8 + rr;
        const float* mrow = memory + ((size_t)b*NN + n)*NM;
        float a0 = mrow[lane], a1 = mrow[lane+32];
        float nrm = a0*a0 + a1*a1;
        float d0 = a0*keys_sh[0*NM+lane] + a1*keys_sh[0*NM+32+lane];
        float d1 = a0*keys_sh[1*NM+lane] + a1*keys_sh[1*NM+32+lane];
        float d2 = a0*keys_sh[2*NM+lane] + a1*keys_sh[2*NM+32+lane];
        float d3 = a0*keys_sh[3*NM+lane] + a1*keys_sh[3*NM+32+lane];
        float d4 = a0*keys_sh[4*NM+lane] + a1*keys_sh[4*NM+32+lane];
        #pragma unroll
        for (int s = 16; s; s >>= 1){
            nrm += __shfl_xor_sync(0xffffffffu, nrm, s);
            d0  += __shfl_xor_sync(0xffffffffu, d0,  s);
            d1  += __shfl_xor_sync(0xffffffffu, d1,  s);
            d2  += __shfl_xor_sync(0xffffffffu, d2,  s);
            d3  += __shfl_xor_sync(0xffffffffu, d3,  s);
            d4  += __shfl_xor_sync(0xffffffffu, d4,  s);
        }
        if (lane == 0){
            float mn = sqrtf(nrm);
            float dd[5] = {d0,d1,d2,d3,d4};
            #pragma unroll
            for (int k = 0; k < 5; k++)
                g_cw[((size_t)b*NKEYS + k)*NN + n] = beta_sh[k]*dd[k]/(kn_sh[k]*mn + FEPS);
        }
    }
}

// ================= K4: softmax stats + usage + allocation + ww + precedence ====
__global__ void k_allocw(const float* __restrict__ pu, const float* __restrict__ pww,
                         const float* __restrict__ prw, const float* __restrict__ prec,
                         float* __restrict__ outU, float* __restrict__ outP){
    __shared__ unsigned long long sk[NN];   // (usage_bits<<32)|index — stable ascending
    __shared__ float cA[NN];
    __shared__ float cB[NN];
    __shared__ float red[1024];
    __shared__ float red32[32];
    __shared__ float bcast;
    __shared__ float stat_sh[NKEYS*2];      // max, inv-sum per key
    int b = blockIdx.x, tid = threadIdx.x;   // 1024 threads
    int warp = tid >> 5, lane = tid & 31;

    // ---- softmax stats for all 5 keys (logits stay raw in g_cw) ----
    for (int k = 0; k < NKEYS; k++){
        const float* p = g_cw + ((size_t)b*NKEYS + k)*NN;
        float v0 = p[tid], v1 = p[tid + 1024];
        float mx = fmaxf(v0, v1);
        #pragma unroll
        for (int s = 16; s; s >>= 1) mx = fmaxf(mx, __shfl_xor_sync(0xffffffffu, mx, s));
        if (lane == 0) red32[warp] = mx;
        __syncthreads();
        if (warp == 0){
            float m = red32[lane];
            #pragma unroll
            for (int s = 16; s; s >>= 1) m = fmaxf(m, __shfl_xor_sync(0xffffffffu, m, s));
            if (lane == 0) bcast = m;
        }
        __syncthreads();
        float M = bcast;
        float sm = expf(v0 - M) + expf(v1 - M);
        #pragma unroll
        for (int s = 16; s; s >>= 1) sm += __shfl_xor_sync(0xffffffffu, sm, s);
        if (lane == 0) red32[warp] = sm;
        __syncthreads();
        if (warp == 0){
            float m = red32[lane];
            #pragma unroll
            for (int s = 16; s; s >>= 1) m += __shfl_xor_sync(0xffffffffu, m, s);
            if (lane == 0){
                stat_sh[k*2] = M; stat_sh[k*2+1] = 1.0f/m;
                g_sstat[b*(NKEYS*2) + k*2]     = M;
                g_sstat[b*(NKEYS*2) + k*2 + 1] = 1.0f/m;
            }
        }
        __syncthreads();
    }

    // ---- usage ----
    float fr0 = g_free[b*NR+0], fr1 = g_free[b*NR+1], fr2 = g_free[b*NR+2], fr3 = g_free[b*NR+3];
    #pragma unroll
    for (int rep = 0; rep < 2; rep++){
        int i = tid + rep*1024;
        float psi = (1.0f - fr0*prw[((size_t)b*NR+0)*NN+i])
                  * (1.0f - fr1*prw[((size_t)b*NR+1)*NN+i])
                  * (1.0f - fr2*prw[((size_t)b*NR+2)*NN+i])
                  * (1.0f - fr3*prw[((size_t)b*NR+3)*NN+i]);
        float u = pu[b*NN+i], w = pww[b*NN+i];
        float usage = (u + w - u*w)*psi;
        outU[b*NN+i] = usage;
        sk[i] = ((unsigned long long)__float_as_uint(usage) << 32) | (unsigned)i;
    }
    __syncthreads();

    // ---- bitonic sort, hybrid smem/register ----
    {
        // stages k=2..32: entirely in-warp (j<=16)
        unsigned long long e0 = sk[tid], e1 = sk[tid + 1024];
        #pragma unroll
        for (int k = 2; k <= 32; k <<= 1){
            #pragma unroll
            for (int j = k >> 1; j > 0; j >>= 1){
                e0 = bsub(e0, tid, j, k);
                e1 = bsub(e1, tid + 1024, j, k);
            }
        }
        sk[tid] = e0; sk[tid + 1024] = e1;
        __syncthreads();
        // stages k=64..2048: j>=32 via smem, j<=16 fused register phase
        for (int k = 64; k <= NN; k <<= 1){
            for (int j = k >> 1; j >= 32; j >>= 1){
                #pragma unroll
                for (int rep = 0; rep < 2; rep++){
                    int i = tid + rep*1024;
                    int p = i ^ j;
                    if (p > i){
                        unsigned long long a = sk[i], bb = sk[p];
                        bool up = ((i & k) == 0);
                        if (up == (a > bb)){ sk[i] = bb; sk[p] = a; }
                    }
                }
                __syncthreads();
            }
            e0 = sk[tid]; e1 = sk[tid + 1024];
            #pragma unroll
            for (int j = 16; j > 0; j >>= 1){
                e0 = bsub(e0, tid, j, k);
                e1 = bsub(e1, tid + 1024, j, k);
            }
            sk[tid] = e0; sk[tid + 1024] = e1;
            __syncthreads();
        }
    }

    #pragma unroll
    for (int rep = 0; rep < 2; rep++){
        int i = tid + rep*1024;
        cA[i] = __uint_as_float((unsigned)(sk[i] >> 32));
    }
    __syncthreads();
    float* src = cA; float* dst = cB;
    for (int off = 1; off < NN; off <<= 1){
        #pragma unroll
        for (int rep = 0; rep < 2; rep++){
            int i = tid + rep*1024;
            dst[i] = (i >= off) ? src[i]*src[i-off] : src[i];
        }
        __syncthreads();
        float* t = src; src = dst; dst = t;
    }
    float ag = g_agate[b], wg = g_wgate[b];
    float M4 = stat_sh[4*2], inv4 = stat_sh[4*2+1];
    const float* cww = g_cw + ((size_t)b*NKEYS + 4)*NN;
    float s = 0.0f;
    #pragma unroll
    for (int rep = 0; rep < 2; rep++){
        int i = tid + rep*1024;
        float sv = __uint_as_float((unsigned)(sk[i] >> 32));
        int n = (int)(sk[i] & 0xffffffffu);
        float excl = (i == 0) ? 1.0f : src[i-1];
        float alloc = (1.0f - sv)*excl;
        float cwn = expf(cww[n] - M4)*inv4;
        float ww = wg*(ag*alloc + (1.0f-ag)*cwn);
        g_ww[b*NN + n] = ww;
        s += ww;
    }
    red[tid] = s; __syncthreads();
    for (int st = 512; st; st >>= 1){ if (tid < st) red[tid] += red[tid+st]; __syncthreads(); }
    float oms = 1.0f - red[0];
    #pragma unroll
    for (int rep = 0; rep < 2; rep++){
        int n = tid + rep*1024;
        outP[b*NN+n] = oms*prec[b*NN+n] + g_ww[b*NN+n];
    }
}

// ================= K5: fused link update + fwd/bwd + memory update ============
__global__ void __launch_bounds__(512)
k_link(const float* __restrict__ L, const float* __restrict__ prw,
       const float* __restrict__ pnew, float* __restrict__ outL,
       const float* __restrict__ memory, float* __restrict__ outM){
    __shared__ float4 wr4_sh[128];      // prev_read_weights, 4 keys packed per row
    __shared__ float wwr_sh[128];
    __shared__ float fwd_sh[NR][128];
    int b = blockIdx.x >> 4;
    int tile = blockIdx.x & 15;
    int rowbase = tile*128;
    int tid = threadIdx.x, lane = tid & 31;
    for (int i = tid; i < 128; i += 512){
        wwr_sh[i] = g_ww[b*NN + rowbase + i];
        wr4_sh[i] = make_float4(prw[((size_t)b*NR + 0)*NN + rowbase + i],
                                prw[((size_t)b*NR + 1)*NN + rowbase + i],
                                prw[((size_t)b*NR + 2)*NN + rowbase + i],
                                prw[((size_t)b*NR + 3)*NN + rowbase + i]);
        #pragma unroll
        for (int r = 0; r < NR; r++) fwd_sh[r][i] = 0.0f;
    }
    __syncthreads();

    // folded memory erase/write update for this tile's rows
    {
        const float4* M4 = (const float4*)memory;
        float4* O4m = (float4*)outM;
        const float4* e4p = (const float4*)g_erase + b*16;
        const float4* v4p = (const float4*)g_wvec + b*16;
        #pragma unroll
        for (int i = tid; i < 128*16; i += 512){
            int rr = i >> 4, m4 = i & 15;
            size_t idx = ((size_t)b*NN + rowbase + rr)*16 + m4;
            float ww = wwr_sh[rr];
            float4 mm = M4[idx];
            float4 e4 = e4p[m4], v4 = v4p[m4];
            float4 o;
            o.x = mm.x*(1.0f - ww*e4.x) + ww*v4.x;
            o.y = mm.y*(1.0f - ww*e4.y) + ww*v4.y;
            o.z = mm.z*(1.0f - ww*e4.z) + ww*v4.z;
            o.w = mm.w*(1.0f - ww*e4.w) + ww*v4.w;
            O4m[idx] = o;
        }
    }

    int j4 = (tid >> 5)*32 + lane;   // float4 column index 0..511
    float4 pj = ((const float4*)(pnew + (size_t)b*NN))[j4];
    float4 wj = ((const float4*)(g_ww + (size_t)b*NN))[j4];
    float4 aj = make_float4(1.0f-wj.x, 1.0f-wj.y, 1.0f-wj.z, 1.0f-wj.w);
    float4 k0 = ((const float4*)(prw + ((size_t)b*NR+0)*NN))[j4];
    float4 k1 = ((const float4*)(prw + ((size_t)b*NR+1)*NN))[j4];
    float4 k2 = ((const float4*)(prw + ((size_t)b*NR+2)*NN))[j4];
    float4 k3 = ((const float4*)(prw + ((size_t)b*NR+3)*NN))[j4];
    float4 bw0 = make_float4(0,0,0,0), bw1 = bw0, bw2 = bw0, bw3 = bw0;
    const float4* L4 = (const float4*)(L + (size_t)b*NN*NN) + j4;
    float4* O4 = (float4*)(outL + (size_t)b*NN*NN) + j4;
    int c0 = j4 << 2;

    auto process = [&](float4 lv, int r){
        int row = rowbase + r;
        float arr = wwr_sh[r];
        float4 o;
        o.x = fmaf(aj.x - arr, lv.x, arr*pj.x);
        o.y = fmaf(aj.y - arr, lv.y, arr*pj.y);
        o.z = fmaf(aj.z - arr, lv.z, arr*pj.z);
        o.w = fmaf(aj.w - arr, lv.w, arr*pj.w);
        int d = row - c0;
        if ((unsigned)d < 4u){
            if (d == 0) o.x = 0.0f; else if (d == 1) o.y = 0.0f;
            else if (d == 2) o.z = 0.0f; else o.w = 0.0f;
        }
        __stcs(&O4[(size_t)row*(NN/4)], o);
        float f0 = lv.x*k0.x + lv.y*k0.y + lv.z*k0.z + lv.w*k0.w;
        float f1 = lv.x*k1.x + lv.y*k1.y + lv.z*k1.z + lv.w*k1.w;
        float f2 = lv.x*k2.x + lv.y*k2.y + lv.z*k2.z + lv.w*k2.w;
        float f3 = lv.x*k3.x + lv.y*k3.y + lv.z*k3.z + lv.w*k3.w;
        float v = multireduce4(f0, f1, f2, f3, lane);
        if (lane < 4) atomicAdd(&fwd_sh[lane][r], v);
        float4 wr = wr4_sh[r];
        bw0.x = fmaf(wr.x, lv.x, bw0.x); bw0.y = fmaf(wr.x, lv.y, bw0.y);
        bw0.z = fmaf(wr.x, lv.z, bw0.z); bw0.w = fmaf(wr.x, lv.w, bw0.w);
        bw1.x = fmaf(wr.y, lv.x, bw1.x); bw1.y = fmaf(wr.y, lv.y, bw1.y);
        bw1.z = fmaf(wr.y, lv.z, bw1.z); bw1.w = fmaf(wr.y, lv.w, bw1.w);
        bw2.x = fmaf(wr.z, lv.x, bw2.x); bw2.y = fmaf(wr.z, lv.y, bw2.y);
        bw2.z = fmaf(wr.z, lv.z, bw2.z); bw2.w = fmaf(wr.z, lv.w, bw2.w);
        bw3.x = fmaf(wr.w, lv.x, bw3.x); bw3.y = fmaf(wr.w, lv.y, bw3.y);
        bw3.z = fmaf(wr.w, lv.z, bw3.z); bw3.w = fmaf(wr.w, lv.w, bw3.w);
    };

    // depth-2 load pipeline
    float4 l0 = __ldcs(&L4[(size_t)(rowbase + 0)*(NN/4)]);
    float4 l1 = __ldcs(&L4[(size_t)(rowbase + 1)*(NN/4)]);
    for (int r = 0; r < 128; r += 2){
        float4 lvA = l0, lvB = l1;
        if (r < 126){
            l0 = __ldcs(&L4[(size_t)(rowbase + r + 2)*(NN/4)]);
            l1 = __ldcs(&L4[(size_t)(rowbase + r + 3)*(NN/4)]);
        }
        process(lvA, r);
        process(lvB, r + 1);
    }

    float4* slab = (float4*)(g_bwdp + (((size_t)tile*NB + b)*NR)*NN);
    slab[0*(NN/4) + j4] = bw0;
    slab[1*(NN/4) + j4] = bw1;
    slab[2*(NN/4) + j4] = bw2;
    slab[3*(NN/4) + j4] = bw3;

    __syncthreads();
    for (int i = tid; i < NR*128; i += 512){
        int r = i >> 7, rr = i & 127;
        g_fwd[((size_t)b*NR + r)*NN + rowbase + rr] = fwd_sh[r][rr];
    }
}

// ================= K6: read weights (inline softmax) + partial reads ===========
__global__ void k_readw(const float* __restrict__ memory, float* __restrict__ outRW){
    __shared__ float rw_sh[4*256];
    __shared__ float red_sh[NR*NM];   // 256
    __shared__ float modes_sh[12];
    __shared__ float stat_sh[8];      // max, invsum for keys 0..3
    int b = blockIdx.x >> 3;
    int chunk = (blockIdx.x & 7)*256;
    int tid = threadIdx.x;
    if (tid < NR){
        float a = g_modes[b*12 + tid*3 + 0];
        float bb = g_modes[b*12 + tid*3 + 1];
        float cc = g_modes[b*12 + tid*3 + 2];
        float mx = fmaxf(a, fmaxf(bb, cc));
        float e0 = expf(a-mx), e1 = expf(bb-mx), e2 = expf(cc-mx);
        float s = 1.0f/(e0+e1+e2);
        modes_sh[tid*3+0] = e0*s; modes_sh[tid*3+1] = e1*s; modes_sh[tid*3+2] = e2*s;
    }
    if (tid < 8) stat_sh[tid] = g_sstat[b*(NKEYS*2) + tid];
    red_sh[tid] = 0.0f;
    __syncthreads();
    for (int i = tid; i < 4*256; i += 256){
        int r = i >> 8, nn = i & 255;
        int n = chunk + nn;
        float bsum = 0.0f;
        #pragma unroll
        for (int t = 0; t < NTILE; t++)
            bsum += g_bwdp[(((size_t)t*NB + b)*NR + r)*NN + n];
        float logit = g_cw[((size_t)b*NKEYS + r)*NN + n];
        float cwv = expf(logit - stat_sh[r*2])*stat_sh[r*2+1];
        float m0 = modes_sh[r*3+0], m1 = modes_sh[r*3+1], m2 = modes_sh[r*3+2];
        float rw = m0*bsum + m1*cwv + m2*g_fwd[((size_t)b*NR + r)*NN + n];
        rw_sh[i] = rw;
        outRW[(size_t)b*NR*NN + (size_t)r*NN + n] = rw;
    }
    __syncthreads();
    int warp = tid >> 5, lane = tid & 31;
    float a00=0,a01=0,a10=0,a11=0,a20=0,a21=0,a30=0,a31=0;
    for (int nn = warp; nn < 256; nn += 8){
        int n = chunk + nn;
        const float* mrow = memory + ((size_t)b*NN + n)*NM;
        float v0 = mrow[lane], v1 = mrow[lane+32];
        float r0 = rw_sh[nn], r1 = rw_sh[256+nn], r2 = rw_sh[512+nn], r3 = rw_sh[768+nn];
        a00 = fmaf(r0, v0, a00); a01 = fmaf(r0, v1, a01);
        a10 = fmaf(r1, v0, a10); a11 = fmaf(r1, v1, a11);
        a20 = fmaf(r2, v0, a20); a21 = fmaf(r2, v1, a21);
        a30 = fmaf(r3, v0, a30); a31 = fmaf(r3, v1, a31);
    }
    atomicAdd(&red_sh[0*NM + lane],      a00); atomicAdd(&red_sh[0*NM + lane + 32], a01);
    atomicAdd(&red_sh[1*NM + lane],      a10); atomicAdd(&red_sh[1*NM + lane + 32], a11);
    atomicAdd(&red_sh[2*NM + lane],      a20); atomicAdd(&red_sh[2*NM + lane + 32], a21);
    atomicAdd(&red_sh[3*NM + lane],      a30); atomicAdd(&red_sh[3*NM + lane + 32], a31);
    __syncthreads();
    atomicAdd(&g_reads[b*(NR*NM) + tid], red_sh[tid]);
}

// ================= K7: read projection + final output (16 blocks) =============
__global__ void k_read2(const float* __restrict__ W_read, const float* __restrict__ b_read,
                        float* __restrict__ outO){
    __shared__ float reads_sh[NR*NM];
    int b = blockIdx.x, tid = threadIdx.x;  // 64 threads
    for (int i = tid; i < NR*NM; i += 64) reads_sh[i] = g_reads[b*(NR*NM) + i];
    __syncthreads();
    float acc = b_read[tid];
    #pragma unroll 8
    for (int k = 0; k < NR*NM; k++)
        acc += W_read[tid*(NR*NM) + k]*reads_sh[k];
    float ro = sigm(acc);
    outO[b*64 + tid] = sigm(ro + g_taskout[b*64 + tid]);
}

// ================= launch =================
extern "C" void kernel_launch(void* const* d_in, const int* in_sizes, int n_in,
                              void* d_out, int out_size){
    const float* task       = (const float*)d_in[0];
    const float* memory     = (const float*)d_in[1];
    const float* L          = (const float*)d_in[2];
    const float* prev_reads = (const float*)d_in[3];
    const float* prw        = (const float*)d_in[4];
    const float* pu         = (const float*)d_in[5];
    const float* pww        = (const float*)d_in[6];
    const float* prec       = (const float*)d_in[7];
    const float* h_prev     = (const float*)d_in[8];
    const float* c_prev     = (const float*)d_in[9];
    const float* W_ih       = (const float*)d_in[10];
    const float* W_hh       = (const float*)d_in[11];
    const float* b_lstm     = (const float*)d_in[12];
    const float* W_out      = (const float*)d_in[13];
    const float* b_out      = (const float*)d_in[14];
    const float* W_read     = (const float*)d_in[15];
    const float* b_read     = (const float*)d_in[16];

    float* out   = (float*)d_out;
    float* outO  = out + OUT_OUTPUT;
    float* outM  = out + OUT_MEM;
    float* outL  = out + OUT_LINK;
    float* outP  = out + OUT_P;
    float* outU  = out + OUT_USAGE;
    float* outRW = out + OUT_READW;

    k_gates  <<<1024, 256>>>(task, prev_reads, h_prev, W_ih, W_hh, b_lstm);
    k_ctrl   <<<NB*4, 512>>>(c_prev, W_out, b_out);
    k_sim    <<<512, 256>>>(memory);
    k_allocw <<<NB, 1024>>>(pu, pww, prw, prec, outU, outP);
    k_link   <<<NB*NTILE, 512>>>(L, prw, outP, outL, memory, outM);
    k_readw  <<<128, 256>>>(memory, outRW);
    k_read2  <<<NB, 64>>>(W_read, b_read, outO);
}

// round 15
// speedup vs baseline: 1.0623x; 1.0623x over previous
#include <cuda_runtime.h>
#include <math.h>
#include <stdint.h>

#define NB 16
#define NN 2048
#define NM 64
#define NR 4
#define NH 512
#define NCIN 320
#define NCOUT 535
#define NKEYS 5
#define FEPS 1e-8f
#define NTILE 16          // row tiles per batch in k_link (128 rows each)

// ---- output layout (tuple flattened in reference return order) ----
#define OUT_OUTPUT 0
#define OUT_MEM    ((size_t)(NB*64))
#define OUT_LINK   (OUT_MEM + (size_t)NB*NN*NM)
#define OUT_P      (OUT_LINK + (size_t)NB*NN*NN)
#define OUT_USAGE  (OUT_P + (size_t)NB*NN)
#define OUT_READW  (OUT_USAGE + (size_t)NB*NN)

// ---- scratch (static device globals; no allocation) ----
__device__ float g_gates[NB*4*NH];
__device__ float g_keys[NB*NKEYS*NM];
__device__ float g_betas[NB*NKEYS];
__device__ float g_free[NB*NR];
__device__ float g_erase[NB*NM];
__device__ float g_wvec[NB*NM];
__device__ float g_agate[NB];
__device__ float g_wgate[NB];
__device__ float g_modes[NB*NR*3];      // raw logits
__device__ float g_taskout[NB*64];
__device__ float g_cw[NB*NKEYS*NN];     // raw beta*sim logits (never normalized in place)
__device__ float g_sstat[NB*NKEYS*2];   // per (b,key): max, inv-sum
__device__ float g_ww[NB*NN];
__device__ float g_fwd[NB*NR*NN];
__device__ float g_bwdp[(size_t)NTILE*NB*NR*NN];   // per-tile bwd partial slabs
__device__ float g_reads[NB*NR*NM];

__device__ __forceinline__ float sigm(float x){ return 1.0f/(1.0f+expf(-x)); }
__device__ __forceinline__ float softplusf(float x){ return fmaxf(x,0.0f) + log1pf(expf(-fabsf(x))); }

// 4-value warp multireduce: after this, lanes with (lane&3)==c hold sum_c.
__device__ __forceinline__ float multireduce4(float f0, float f1, float f2, float f3, int lane){
    float a01 = (lane & 1) ? f0 : f1;
    float r01 = __shfl_xor_sync(0xffffffffu, a01, 1);
    float u = (lane & 1) ? (f1 + r01) : (f0 + r01);
    float a23 = (lane & 1) ? f2 : f3;
    float r23 = __shfl_xor_sync(0xffffffffu, a23, 1);
    float w = (lane & 1) ? (f3 + r23) : (f2 + r23);
    float a2 = (lane & 2) ? u : w;
    float r2 = __shfl_xor_sync(0xffffffffu, a2, 2);
    float v = (lane & 2) ? (w + r2) : (u + r2);
    v += __shfl_xor_sync(0xffffffffu, v, 4);
    v += __shfl_xor_sync(0xffffffffu, v, 8);
    v += __shfl_xor_sync(0xffffffffu, v, 16);
    return v;
}

// bitonic in-warp substage for element index i, stage k, distance j (j<=16)
__device__ __forceinline__ unsigned long long bsub(unsigned long long e, int i, int j, int k){
    unsigned long long o = __shfl_xor_sync(0xffffffffu, e, j);
    bool takeMin = (((i & j) == 0) == ((i & k) == 0));
    bool gt = e > o;
    return (takeMin == gt) ? o : e;
}

// ================= K1: LSTM gates — warp computes one g for 4 batches =========
__global__ void k_gates(const float* __restrict__ task, const float* __restrict__ prev_reads,
                        const float* __restrict__ h_prev, const float* __restrict__ W_ih,
                        const float* __restrict__ W_hh, const float* __restrict__ b_lstm){
    int w = (blockIdx.x*blockDim.x + threadIdx.x) >> 5;   // 8192 warps
    int lane = threadIdx.x & 31;
    int bg = w & 3;             // batch group (4 batches each)
    int g = w >> 2;             // 0..2047
    int b0 = bg*4;
    float a0 = 0.f, a1 = 0.f, a2 = 0.f, a3 = 0.f;
    const float2* wi = (const float2*)(W_ih + (size_t)g*NCIN);
    const float2* t2 = (const float2*)task;          // [b][32]
    const float2* r2 = (const float2*)prev_reads;    // [b][128]
    #pragma unroll
    for (int k2 = lane, it = 0; it < 5; k2 += 32, it++){
        float2 wv = wi[k2];
        float2 x0, x1, x2, x3;
        if (k2 < 32){
            x0 = t2[(b0+0)*32 + k2]; x1 = t2[(b0+1)*32 + k2];
            x2 = t2[(b0+2)*32 + k2]; x3 = t2[(b0+3)*32 + k2];
        } else {
            int kk = k2 - 32;
            x0 = r2[(b0+0)*128 + kk]; x1 = r2[(b0+1)*128 + kk];
            x2 = r2[(b0+2)*128 + kk]; x3 = r2[(b0+3)*128 + kk];
        }
        a0 = fmaf(wv.x, x0.x, fmaf(wv.y, x0.y, a0));
        a1 = fmaf(wv.x, x1.x, fmaf(wv.y, x1.y, a1));
        a2 = fmaf(wv.x, x2.x, fmaf(wv.y, x2.y, a2));
        a3 = fmaf(wv.x, x3.x, fmaf(wv.y, x3.y, a3));
    }
    const float2* wh = (const float2*)(W_hh + (size_t)g*NH);
    const float2* h2 = (const float2*)h_prev;        // [b][256]
    #pragma unroll
    for (int k2 = lane, it = 0; it < 8; k2 += 32, it++){
        float2 wv = wh[k2];
        float2 x0 = h2[(b0+0)*256 + k2], x1 = h2[(b0+1)*256 + k2];
        float2 x2 = h2[(b0+2)*256 + k2], x3 = h2[(b0+3)*256 + k2];
        a0 = fmaf(wv.x, x0.x, fmaf(wv.y, x0.y, a0));
        a1 = fmaf(wv.x, x1.x, fmaf(wv.y, x1.y, a1));
        a2 = fmaf(wv.x, x2.x, fmaf(wv.y, x2.y, a2));
        a3 = fmaf(wv.x, x3.x, fmaf(wv.y, x3.y, a3));
    }
    float v = multireduce4(a0, a1, a2, a3, lane);
    if (lane < 4) g_gates[(b0 + lane)*(4*NH) + g] = v + b_lstm[g];
}

// ================= K2: fused LSTM cell + output projection + parse =============
__global__ void k_ctrl(const float* __restrict__ c_prev, const float* __restrict__ W_out,
                       const float* __restrict__ b_out){
    __shared__ float h_sh[NH];
    int b = blockIdx.x >> 2;
    int part = blockIdx.x & 3;
    int tid = threadIdx.x;
    if (part == 0 && tid < NR*NM) g_reads[b*(NR*NM) + tid] = 0.0f;
    {
        const float* gb = g_gates + b*(4*NH);
        float gi = gb[tid], gf = gb[NH+tid], gg = gb[2*NH+tid], go = gb[3*NH+tid];
        float c = sigm(gf)*c_prev[b*NH+tid] + sigm(gi)*tanhf(gg);
        h_sh[tid] = sigm(go)*tanhf(c);
    }
    __syncthreads();
    int warp = tid >> 5, lane = tid & 31;
    int gw = part*16 + warp;      // 0..63
    const float2* h2 = (const float2*)h_sh;
    for (int o = gw; o < NCOUT; o += 64){
        float acc = 0.0f;
        const float2* w2 = (const float2*)(W_out + (size_t)o*NH);
        #pragma unroll
        for (int k2 = lane, it = 0; it < 8; k2 += 32, it++){
            float2 wv = w2[k2], xv = h2[k2];
            acc = fmaf(wv.x, xv.x, fmaf(wv.y, xv.y, acc));
        }
        #pragma unroll
        for (int s = 16; s; s >>= 1) acc += __shfl_xor_sync(0xffffffffu, acc, s);
        if (lane == 0){
            float v = acc + b_out[o];
            int c = o;
            if (c < 64)        g_taskout[b*64 + c] = sigm(v);
            else if (c < 320)  g_keys[b*NKEYS*NM + (c-64)] = sigm(v);
            else if (c < 324)  g_betas[b*NKEYS + (c-320)] = 1.0f + softplusf(v);
            else if (c < 328)  g_free[b*NR + (c-324)] = sigm(v);
            else if (c < 392)  g_keys[b*NKEYS*NM + 4*NM + (c-328)] = sigm(v);
            else if (c == 392) g_betas[b*NKEYS + 4] = 1.0f + softplusf(v);
            else if (c < 457)  g_erase[b*NM + (c-393)] = sigm(v);
            else if (c < 521)  g_wvec[b*NM + (c-457)] = sigm(v);
            else if (c == 521) g_agate[b] = sigm(v);
            else if (c == 522) g_wgate[b] = sigm(v);
            else               g_modes[b*12 + (c-523)] = v;
        }
    }
}

// ================= K3: cosine similarity logits (beta*sim), 512 blocks =========
__global__ void k_sim(const float* __restrict__ memory){
    __shared__ float keys_sh[NKEYS*NM];
    __shared__ float beta_sh[NKEYS], kn_sh[NKEYS];
    int b = blockIdx.x >> 5;
    int tile = blockIdx.x & 31;
    int tid = threadIdx.x;
    for (int i = tid; i < NKEYS*NM; i += blockDim.x) keys_sh[i] = g_keys[b*NKEYS*NM + i];
    if (tid < NKEYS) beta_sh[tid] = g_betas[b*NKEYS+tid];
    __syncthreads();
    if (tid < NKEYS){
        float s = 0.0f;
        #pragma unroll 8
        for (int i = 0; i < NM; i++){ float x = keys_sh[tid*NM+i]; s += x*x; }
        kn_sh[tid] = sqrtf(s);
    }
    __syncthreads();
    int warp = tid >> 5, lane = tid & 31;
    #pragma unroll
    for (int rr = 0; rr < 8; rr++){
        int n = tile*64 + warp*8 + rr;
        const float* mrow = memory + ((size_t)b*NN + n)*NM;
        float a0 = mrow[lane], a1 = mrow[lane+32];
        float nrm = a0*a0 + a1*a1;
        float d0 = a0*keys_sh[0*NM+lane] + a1*keys_sh[0*NM+32+lane];
        float d1 = a0*keys_sh[1*NM+lane] + a1*keys_sh[1*NM+32+lane];
        float d2 = a0*keys_sh[2*NM+lane] + a1*keys_sh[2*NM+32+lane];
        float d3 = a0*keys_sh[3*NM+lane] + a1*keys_sh[3*NM+32+lane];
        float d4 = a0*keys_sh[4*NM+lane] + a1*keys_sh[4*NM+32+lane];
        #pragma unroll
        for (int s = 16; s; s >>= 1){
            nrm += __shfl_xor_sync(0xffffffffu, nrm, s);
            d0  += __shfl_xor_sync(0xffffffffu, d0,  s);
            d1  += __shfl_xor_sync(0xffffffffu, d1,  s);
            d2  += __shfl_xor_sync(0xffffffffu, d2,  s);
            d3  += __shfl_xor_sync(0xffffffffu, d3,  s);
            d4  += __shfl_xor_sync(0xffffffffu, d4,  s);
        }
        if (lane == 0){
            float mn = sqrtf(nrm);
            float dd[5] = {d0,d1,d2,d3,d4};
            #pragma unroll
            for (int k = 0; k < 5; k++)
                g_cw[((size_t)b*NKEYS + k)*NN + n] = beta_sh[k]*dd[k]/(kn_sh[k]*mn + FEPS);
        }
    }
}

// ================= K4: softmax stats + usage + allocation + ww + precedence ====
__global__ void k_allocw(const float* __restrict__ pu, const float* __restrict__ pww,
                         const float* __restrict__ prw, const float* __restrict__ prec,
                         float* __restrict__ outU, float* __restrict__ outP){
    __shared__ unsigned long long sk[NN];   // (usage_bits<<32)|index — stable ascending
    __shared__ float cA[NN];
    __shared__ float cB[NN];
    __shared__ float red[1024];
    __shared__ float red5[NKEYS][32];
    __shared__ float stat_sh[NKEYS*2];      // max, inv-sum per key
    int b = blockIdx.x, tid = threadIdx.x;   // 1024 threads
    int warp = tid >> 5, lane = tid & 31;

    // ---- softmax stats for all 5 keys, batched (4 barriers total) ----
    {
        float v0[NKEYS], v1[NKEYS];
        #pragma unroll
        for (int k = 0; k < NKEYS; k++){
            const float* p = g_cw + ((size_t)b*NKEYS + k)*NN;
            v0[k] = p[tid]; v1[k] = p[tid + 1024];
            float m = fmaxf(v0[k], v1[k]);
            #pragma unroll
            for (int s = 16; s; s >>= 1) m = fmaxf(m, __shfl_xor_sync(0xffffffffu, m, s));
            if (lane == 0) red5[k][warp] = m;
        }
        __syncthreads();
        if (warp == 0){
            #pragma unroll
            for (int k = 0; k < NKEYS; k++){
                float m = red5[k][lane];
                #pragma unroll
                for (int s = 16; s; s >>= 1) m = fmaxf(m, __shfl_xor_sync(0xffffffffu, m, s));
                if (lane == 0) stat_sh[k*2] = m;
            }
        }
        __syncthreads();
        #pragma unroll
        for (int k = 0; k < NKEYS; k++){
            float M = stat_sh[k*2];
            float sm = expf(v0[k] - M) + expf(v1[k] - M);
            #pragma unroll
            for (int s = 16; s; s >>= 1) sm += __shfl_xor_sync(0xffffffffu, sm, s);
            if (lane == 0) red5[k][warp] = sm;
        }
        __syncthreads();
        if (warp == 0){
            #pragma unroll
            for (int k = 0; k < NKEYS; k++){
                float m = red5[k][lane];
                #pragma unroll
                for (int s = 16; s; s >>= 1) m += __shfl_xor_sync(0xffffffffu, m, s);
                if (lane == 0){
                    stat_sh[k*2+1] = 1.0f/m;
                    g_sstat[b*(NKEYS*2) + k*2]     = stat_sh[k*2];
                    g_sstat[b*(NKEYS*2) + k*2 + 1] = 1.0f/m;
                }
            }
        }
        __syncthreads();
    }

    // ---- usage ----
    float fr0 = g_free[b*NR+0], fr1 = g_free[b*NR+1], fr2 = g_free[b*NR+2], fr3 = g_free[b*NR+3];
    #pragma unroll
    for (int rep = 0; rep < 2; rep++){
        int i = tid + rep*1024;
        float psi = (1.0f - fr0*prw[((size_t)b*NR+0)*NN+i])
                  * (1.0f - fr1*prw[((size_t)b*NR+1)*NN+i])
                  * (1.0f - fr2*prw[((size_t)b*NR+2)*NN+i])
                  * (1.0f - fr3*prw[((size_t)b*NR+3)*NN+i]);
        float u = pu[b*NN+i], w = pww[b*NN+i];
        float usage = (u + w - u*w)*psi;
        outU[b*NN+i] = usage;
        sk[i] = ((unsigned long long)__float_as_uint(usage) << 32) | (unsigned)i;
    }
    __syncthreads();

    // ---- bitonic sort, hybrid smem/register ----
    {
        unsigned long long e0 = sk[tid], e1 = sk[tid + 1024];
        #pragma unroll
        for (int k = 2; k <= 32; k <<= 1){
            #pragma unroll
            for (int j = k >> 1; j > 0; j >>= 1){
                e0 = bsub(e0, tid, j, k);
                e1 = bsub(e1, tid + 1024, j, k);
            }
        }
        sk[tid] = e0; sk[tid + 1024] = e1;
        __syncthreads();
        for (int k = 64; k <= NN; k <<= 1){
            for (int j = k >> 1; j >= 32; j >>= 1){
                #pragma unroll
                for (int rep = 0; rep < 2; rep++){
                    int i = tid + rep*1024;
                    int p = i ^ j;
                    if (p > i){
                        unsigned long long a = sk[i], bb = sk[p];
                        bool up = ((i & k) == 0);
                        if (up == (a > bb)){ sk[i] = bb; sk[p] = a; }
                    }
                }
                __syncthreads();
            }
            e0 = sk[tid]; e1 = sk[tid + 1024];
            #pragma unroll
            for (int j = 16; j > 0; j >>= 1){
                e0 = bsub(e0, tid, j, k);
                e1 = bsub(e1, tid + 1024, j, k);
            }
            sk[tid] = e0; sk[tid + 1024] = e1;
            __syncthreads();
        }
    }

    #pragma unroll
    for (int rep = 0; rep < 2; rep++){
        int i = tid + rep*1024;
        cA[i] = __uint_as_float((unsigned)(sk[i] >> 32));
    }
    __syncthreads();
    float* src = cA; float* dst = cB;
    for (int off = 1; off < NN; off <<= 1){
        #pragma unroll
        for (int rep = 0; rep < 2; rep++){
            int i = tid + rep*1024;
            dst[i] = (i >= off) ? src[i]*src[i-off] : src[i];
        }
        __syncthreads();
        float* t = src; src = dst; dst = t;
    }
    float ag = g_agate[b], wg = g_wgate[b];
    float M4 = stat_sh[4*2], inv4 = stat_sh[4*2+1];
    const float* cww = g_cw + ((size_t)b*NKEYS + 4)*NN;
    float s = 0.0f;
    #pragma unroll
    for (int rep = 0; rep < 2; rep++){
        int i = tid + rep*1024;
        float sv = __uint_as_float((unsigned)(sk[i] >> 32));
        int n = (int)(sk[i] & 0xffffffffu);
        float excl = (i == 0) ? 1.0f : src[i-1];
        float alloc = (1.0f - sv)*excl;
        float cwn = expf(cww[n] - M4)*inv4;
        float ww = wg*(ag*alloc + (1.0f-ag)*cwn);
        g_ww[b*NN + n] = ww;
        s += ww;
    }
    red[tid] = s; __syncthreads();
    for (int st = 512; st; st >>= 1){ if (tid < st) red[tid] += red[tid+st]; __syncthreads(); }
    float oms = 1.0f - red[0];
    #pragma unroll
    for (int rep = 0; rep < 2; rep++){
        int n = tid + rep*1024;
        outP[b*NN+n] = oms*prec[b*NN+n] + g_ww[b*NN+n];
    }
}

// ================= K5: fused link update + fwd/bwd + memory update (R11 form) ==
__global__ void __launch_bounds__(512)
k_link(const float* __restrict__ L, const float* __restrict__ prw,
       const float* __restrict__ pnew, float* __restrict__ outL,
       const float* __restrict__ memory, float* __restrict__ outM){
    __shared__ float wr_sh[NR][128];
    __shared__ float wwr_sh[128];
    __shared__ float fwd_sh[NR][128];
    int b = blockIdx.x >> 4;
    int tile = blockIdx.x & 15;
    int rowbase = tile*128;
    int tid = threadIdx.x, lane = tid & 31;
    for (int i = tid; i < 128; i += 512){
        wwr_sh[i] = g_ww[b*NN + rowbase + i];
        #pragma unroll
        for (int r = 0; r < NR; r++){
            wr_sh[r][i] = prw[((size_t)b*NR + r)*NN + rowbase + i];
            fwd_sh[r][i] = 0.0f;
        }
    }
    __syncthreads();

    // folded memory erase/write update for this tile's rows
    {
        const float4* M4 = (const float4*)memory;
        float4* O4m = (float4*)outM;
        const float4* e4p = (const float4*)g_erase + b*16;
        const float4* v4p = (const float4*)g_wvec + b*16;
        #pragma unroll
        for (int i = tid; i < 128*16; i += 512){
            int rr = i >> 4, m4 = i & 15;
            size_t idx = ((size_t)b*NN + rowbase + rr)*16 + m4;
            float ww = wwr_sh[rr];
            float4 mm = M4[idx];
            float4 e4 = e4p[m4], v4 = v4p[m4];
            float4 o;
            o.x = mm.x*(1.0f - ww*e4.x) + ww*v4.x;
            o.y = mm.y*(1.0f - ww*e4.y) + ww*v4.y;
            o.z = mm.z*(1.0f - ww*e4.z) + ww*v4.z;
            o.w = mm.w*(1.0f - ww*e4.w) + ww*v4.w;
            O4m[idx] = o;
        }
    }

    int j4 = (tid >> 5)*32 + lane;   // float4 column index 0..511
    float4 pj = ((const float4*)(pnew + (size_t)b*NN))[j4];
    float4 wj = ((const float4*)(g_ww + (size_t)b*NN))[j4];
    float4 aj = make_float4(1.0f-wj.x, 1.0f-wj.y, 1.0f-wj.z, 1.0f-wj.w);
    float4 k0 = ((const float4*)(prw + ((size_t)b*NR+0)*NN))[j4];
    float4 k1 = ((const float4*)(prw + ((size_t)b*NR+1)*NN))[j4];
    float4 k2 = ((const float4*)(prw + ((size_t)b*NR+2)*NN))[j4];
    float4 k3 = ((const float4*)(prw + ((size_t)b*NR+3)*NN))[j4];
    float4 bw0 = make_float4(0,0,0,0), bw1 = bw0, bw2 = bw0, bw3 = bw0;
    const float4* L4 = (const float4*)(L + (size_t)b*NN*NN) + j4;
    float4* O4 = (float4*)(outL + (size_t)b*NN*NN) + j4;
    int c0 = j4 << 2;

    float4 l = __ldcs(&L4[(size_t)rowbase*(NN/4)]);
    for (int r = 0; r < 128; r++){
        int row = rowbase + r;
        float4 lv = l;
        if (r < 127) l = __ldcs(&L4[(size_t)(row+1)*(NN/4)]);
        float arr = wwr_sh[r];
        float4 o;
        o.x = fmaf(aj.x - arr, lv.x, arr*pj.x);
        o.y = fmaf(aj.y - arr, lv.y, arr*pj.y);
        o.z = fmaf(aj.z - arr, lv.z, arr*pj.z);
        o.w = fmaf(aj.w - arr, lv.w, arr*pj.w);
        int d = row - c0;
        if ((unsigned)d < 4u){
            if (d == 0) o.x = 0.0f; else if (d == 1) o.y = 0.0f;
            else if (d == 2) o.z = 0.0f; else o.w = 0.0f;
        }
        __stcs(&O4[(size_t)row*(NN/4)], o);
        float f0 = lv.x*k0.x + lv.y*k0.y + lv.z*k0.z + lv.w*k0.w;
        float f1 = lv.x*k1.x + lv.y*k1.y + lv.z*k1.z + lv.w*k1.w;
        float f2 = lv.x*k2.x + lv.y*k2.y + lv.z*k2.z + lv.w*k2.w;
        float f3 = lv.x*k3.x + lv.y*k3.y + lv.z*k3.z + lv.w*k3.w;
        float v = multireduce4(f0, f1, f2, f3, lane);
        if (lane < 4) atomicAdd(&fwd_sh[lane][r], v);
        float w0 = wr_sh[0][r], w1 = wr_sh[1][r], w2 = wr_sh[2][r], w3 = wr_sh[3][r];
        bw0.x = fmaf(w0, lv.x, bw0.x); bw0.y = fmaf(w0, lv.y, bw0.y);
        bw0.z = fmaf(w0, lv.z, bw0.z); bw0.w = fmaf(w0, lv.w, bw0.w);
        bw1.x = fmaf(w1, lv.x, bw1.x); bw1.y = fmaf(w1, lv.y, bw1.y);
        bw1.z = fmaf(w1, lv.z, bw1.z); bw1.w = fmaf(w1, lv.w, bw1.w);
        bw2.x = fmaf(w2, lv.x, bw2.x); bw2.y = fmaf(w2, lv.y, bw2.y);
        bw2.z = fmaf(w2, lv.z, bw2.z); bw2.w = fmaf(w2, lv.w, bw2.w);
        bw3.x = fmaf(w3, lv.x, bw3.x); bw3.y = fmaf(w3, lv.y, bw3.y);
        bw3.z = fmaf(w3, lv.z, bw3.z); bw3.w = fmaf(w3, lv.w, bw3.w);
    }

    float4* slab = (float4*)(g_bwdp + (((size_t)tile*NB + b)*NR)*NN);
    slab[0*(NN/4) + j4] = bw0;
    slab[1*(NN/4) + j4] = bw1;
    slab[2*(NN/4) + j4] = bw2;
    slab[3*(NN/4) + j4] = bw3;

    __syncthreads();
    for (int i = tid; i < NR*128; i += 512){
        int r = i >> 7, rr = i & 127;
        g_fwd[((size_t)b*NR + r)*NN + rowbase + rr] = fwd_sh[r][rr];
    }
}

// ================= K6: read weights (inline softmax) + partial reads ===========
__global__ void k_readw(const float* __restrict__ memory, float* __restrict__ outRW){
    __shared__ float rw_sh[4*256];
    __shared__ float red_sh[NR*NM];   // 256
    __shared__ float modes_sh[12];
    __shared__ float stat_sh[8];      // max, invsum for keys 0..3
    int b = blockIdx.x >> 3;
    int chunk = (blockIdx.x & 7)*256;
    int tid = threadIdx.x;
    if (tid < NR){
        float a = g_modes[b*12 + tid*3 + 0];
        float bb = g_modes[b*12 + tid*3 + 1];
        float cc = g_modes[b*12 + tid*3 + 2];
        float mx = fmaxf(a, fmaxf(bb, cc));
        float e0 = expf(a-mx), e1 = expf(bb-mx), e2 = expf(cc-mx);
        float s = 1.0f/(e0+e1+e2);
        modes_sh[tid*3+0] = e0*s; modes_sh[tid*3+1] = e1*s; modes_sh[tid*3+2] = e2*s;
    }
    if (tid < 8) stat_sh[tid] = g_sstat[b*(NKEYS*2) + tid];
    red_sh[tid] = 0.0f;
    __syncthreads();
    for (int i = tid; i < 4*256; i += 256){
        int r = i >> 8, nn = i & 255;
        int n = chunk + nn;
        float bsum = 0.0f;
        #pragma unroll
        for (int t = 0; t < NTILE; t++)
            bsum += g_bwdp[(((size_t)t*NB + b)*NR + r)*NN + n];
        float logit = g_cw[((size_t)b*NKEYS + r)*NN + n];
        float cwv = expf(logit - stat_sh[r*2])*stat_sh[r*2+1];
        float m0 = modes_sh[r*3+0], m1 = modes_sh[r*3+1], m2 = modes_sh[r*3+2];
        float rw = m0*bsum + m1*cwv + m2*g_fwd[((size_t)b*NR + r)*NN + n];
        rw_sh[i] = rw;
        outRW[(size_t)b*NR*NN + (size_t)r*NN + n] = rw;
    }
    __syncthreads();
    int warp = tid >> 5, lane = tid & 31;
    float a00=0,a01=0,a10=0,a11=0,a20=0,a21=0,a30=0,a31=0;
    for (int nn = warp; nn < 256; nn += 8){
        int n = chunk + nn;
        const float* mrow = memory + ((size_t)b*NN + n)*NM;
        float v0 = mrow[lane], v1 = mrow[lane+32];
        float r0 = rw_sh[nn], r1 = rw_sh[256+nn], r2 = rw_sh[512+nn], r3 = rw_sh[768+nn];
        a00 = fmaf(r0, v0, a00); a01 = fmaf(r0, v1, a01);
        a10 = fmaf(r1, v0, a10); a11 = fmaf(r1, v1, a11);
        a20 = fmaf(r2, v0, a20); a21 = fmaf(r2, v1, a21);
        a30 = fmaf(r3, v0, a30); a31 = fmaf(r3, v1, a31);
    }
    atomicAdd(&red_sh[0*NM + lane],      a00); atomicAdd(&red_sh[0*NM + lane + 32], a01);
    atomicAdd(&red_sh[1*NM + lane],      a10); atomicAdd(&red_sh[1*NM + lane + 32], a11);
    atomicAdd(&red_sh[2*NM + lane],      a20); atomicAdd(&red_sh[2*NM + lane + 32], a21);
    atomicAdd(&red_sh[3*NM + lane],      a30); atomicAdd(&red_sh[3*NM + lane + 32], a31);
    __syncthreads();
    atomicAdd(&g_reads[b*(NR*NM) + tid], red_sh[tid]);
}

// ================= K7: read projection + final output (16 blocks) =============
__global__ void k_read2(const float* __restrict__ W_read, const float* __restrict__ b_read,
                        float* __restrict__ outO){
    __shared__ float reads_sh[NR*NM];
    int b = blockIdx.x, tid = threadIdx.x;  // 64 threads
    for (int i = tid; i < NR*NM; i += 64) reads_sh[i] = g_reads[b*(NR*NM) + i];
    __syncthreads();
    float acc = b_read[tid];
    #pragma unroll 8
    for (int k = 0; k < NR*NM; k++)
        acc += W_read[tid*(NR*NM) + k]*reads_sh[k];
    float ro = sigm(acc);
    outO[b*64 + tid] = sigm(ro + g_taskout[b*64 + tid]);
}

// ================= launch =================
extern "C" void kernel_launch(void* const* d_in, const int* in_sizes, int n_in,
                              void* d_out, int out_size){
    const float* task       = (const float*)d_in[0];
    const float* memory     = (const float*)d_in[1];
    const float* L          = (const float*)d_in[2];
    const float* prev_reads = (const float*)d_in[3];
    const float* prw        = (const float*)d_in[4];
    const float* pu         = (const float*)d_in[5];
    const float* pww        = (const float*)d_in[6];
    const float* prec       = (const float*)d_in[7];
    const float* h_prev     = (const float*)d_in[8];
    const float* c_prev     = (const float*)d_in[9];
    const float* W_ih       = (const float*)d_in[10];
    const float* W_hh       = (const float*)d_in[11];
    const float* b_lstm     = (const float*)d_in[12];
    const float* W_out      = (const float*)d_in[13];
    const float* b_out      = (const float*)d_in[14];
    const float* W_read     = (const float*)d_in[15];
    const float* b_read     = (const float*)d_in[16];

    float* out   = (float*)d_out;
    float* outO  = out + OUT_OUTPUT;
    float* outM  = out + OUT_MEM;
    float* outL  = out + OUT_LINK;
    float* outP  = out + OUT_P;
    float* outU  = out + OUT_USAGE;
    float* outRW = out + OUT_READW;

    k_gates  <<<1024, 256>>>(task, prev_reads, h_prev, W_ih, W_hh, b_lstm);
    k_ctrl   <<<NB*4, 512>>>(c_prev, W_out, b_out);
    k_sim    <<<512, 256>>>(memory);
    k_allocw <<<NB, 1024>>>(pu, pww, prw, prec, outU, outP);
    k_link   <<<NB*NTILE, 512>>>(L, prw, outP, outL, memory, outM);
    k_readw  <<<128, 256>>>(memory, outRW);
    k_read2  <<<NB, 64>>>(W_read, b_read, outO);
}